// round 2
// baseline (speedup 1.0000x reference)
#include <cuda_runtime.h>
#include <math.h>

// Problem constants
#define CB 4
#define CN 1024
#define CDIM 512
#define CH 8
#define CD 64
#define CINNER 512
#define CBH (CB*CH)          // 32
#define CMTOT (CB*CN)        // 4096
#define CSCALE 0.125f        // 64^-0.5

// ---------------- scratch (allocation-free: __device__ globals) ----------------
__device__ float g_qr[CBH*CN*CD];
__device__ float g_qi[CBH*CN*CD];
__device__ float g_kr[CBH*CN*CD];
__device__ float g_ki[CBH*CN*CD];
__device__ float g_vr[CBH*CN*CD];
__device__ float g_vi[CBH*CN*CD];
__device__ float g_ar[CMTOT*CINNER];   // attention out (real), [b][n][h*64+d]
__device__ float g_ai[CMTOT*CINNER];   // attention out (imag)

// =====================================================================
// Kernel 1: fused complex QKV projection.
//   A = x  [4096 rows, 512 k] complex (float2 interleaved)
//   B = [wq (512 cols) | wkv (1024 cols)] complex
//   outputs scattered to planar q/k/v [bh][n][d]
// =====================================================================
__global__ __launch_bounds__(256) void k_proj_qkv(
    const float2* __restrict__ x,
    const float* __restrict__ wq_r, const float* __restrict__ wq_i,
    const float* __restrict__ wkv_r, const float* __restrict__ wkv_i)
{
    __shared__ float Asr[16][65], Asi[16][65], Bsr[16][65], Bsi[16][65];
    const int m0 = blockIdx.x * 64;
    const int c0 = blockIdx.y * 64;            // complex output col tile (0..1535)
    const int tid = threadIdx.x;
    const int ti = tid >> 4, tj = tid & 15;
    float cr[4][4] = {}, ci[4][4] = {};

    for (int k0 = 0; k0 < CDIM; k0 += 16) {
        #pragma unroll
        for (int it = 0; it < 4; ++it) {
            int idx = it*256 + tid;
            int row = idx >> 4, kk = idx & 15;
            float2 v = x[(size_t)(m0+row)*CDIM + k0 + kk];
            Asr[kk][row] = v.x; Asi[kk][row] = v.y;
        }
        #pragma unroll
        for (int it = 0; it < 4; ++it) {
            int idx = it*256 + tid;
            int kk = idx >> 6, c = idx & 63;
            int cg = c0 + c, krw = k0 + kk;
            float br, bi;
            if (cg < 512) { br = wq_r[krw*512 + cg];          bi = wq_i[krw*512 + cg]; }
            else          { br = wkv_r[krw*1024 + (cg-512)];  bi = wkv_i[krw*1024 + (cg-512)]; }
            Bsr[kk][c] = br; Bsi[kk][c] = bi;
        }
        __syncthreads();
        #pragma unroll
        for (int kk = 0; kk < 16; ++kk) {
            float ar[4], ai[4], br[4], bi[4];
            #pragma unroll
            for (int i = 0; i < 4; ++i) { ar[i]=Asr[kk][ti*4+i]; ai[i]=Asi[kk][ti*4+i]; }
            #pragma unroll
            for (int j = 0; j < 4; ++j) { br[j]=Bsr[kk][tj*4+j]; bi[j]=Bsi[kk][tj*4+j]; }
            #pragma unroll
            for (int i = 0; i < 4; ++i)
            #pragma unroll
            for (int j = 0; j < 4; ++j) {
                cr[i][j] += ar[i]*br[j] - ai[i]*bi[j];
                ci[i][j] += ai[i]*br[j] + ar[i]*bi[j];
            }
        }
        __syncthreads();
    }
    #pragma unroll
    for (int i = 0; i < 4; ++i) {
        int m = m0 + ti*4 + i;
        int b = m >> 10, n = m & 1023;
        #pragma unroll
        for (int j = 0; j < 4; ++j) {
            int cg = c0 + tj*4 + j;
            float r = cr[i][j], im = ci[i][j];
            int local = cg & 511;              // works for all three ranges
            int h = local >> 6, d = local & 63;
            size_t o = (((size_t)b*CH + h)*CN + n)*CD + d;
            if (cg < 512)       { g_qr[o] = r; g_qi[o] = im; }
            else if (cg < 1024) { g_kr[o] = r; g_ki[o] = im; }
            else                { g_vr[o] = r; g_vi[o] = im; }
        }
    }
}

// =====================================================================
// Kernel 2: fused complex attention with magnitude online-softmax.
// Per block: one (b,h) and one 64-row query tile; loop over 16 key tiles.
// Rel-position handled per tile-pair via E[ii,t]=q[ii]·rel_row[t] GEMM +
// anti-diagonal gather (t = ii-jj+63).
// =====================================================================
#define ATTN_SMEM_FLOATS 46912
#define ATTN_SMEM_BYTES  (ATTN_SMEM_FLOATS*4)

__global__ __launch_bounds__(256) void k_attn(const float* __restrict__ rel_emb)
{
    extern __shared__ float sm[];
    float* sQr   = sm;                 // 64*65
    float* sQi   = sQr + 4160;
    float* sKr   = sQi + 4160;
    float* sKi   = sKr + 4160;
    float* sVr   = sKi + 4160;
    float* sVi   = sVr + 4160;
    float* sRel  = sVi + 4160;         // 128*65
    float* sE    = sRel + 8320;        // 64*129
    float* sP    = sE + 8256;          // 64*65
    float* rowMax= sP + 4160;          // 64
    float* rowL  = rowMax + 64;        // 64
    float* alpha = rowL + 64;          // 64
    float* sRed  = alpha + 64;         // 64*16

    const int bh = blockIdx.x;         // 0..31
    const int i0 = blockIdx.y * 64;    // query tile start
    const int tid = threadIdx.x;
    const int ti = tid >> 4, tj = tid & 15;

    #pragma unroll
    for (int it = 0; it < 16; ++it) {
        int idx = it*256 + tid;
        int row = idx >> 6, d = idx & 63;
        size_t g = ((size_t)bh*CN + i0 + row)*CD + d;
        sQr[row*65 + d] = g_qr[g];
        sQi[row*65 + d] = g_qi[g];
    }
    if (tid < 64) { rowMax[tid] = -1e30f; rowL[tid] = 0.f; }
    float o_r[4][4] = {}, o_i[4][4] = {};
    __syncthreads();

    for (int jt = 0; jt < 16; ++jt) {
        const int j0 = jt * 64;
        #pragma unroll
        for (int it = 0; it < 16; ++it) {
            int idx = it*256 + tid;
            int row = idx >> 6, d = idx & 63;
            size_t g = ((size_t)bh*CN + j0 + row)*CD + d;
            sKr[row*65+d] = g_kr[g];
            sKi[row*65+d] = g_ki[g];
            sVr[row*65+d] = g_vr[g];
            sVi[row*65+d] = g_vi[g];
        }
        const int base = i0 - j0;
        #pragma unroll
        for (int it = 0; it < 32; ++it) {
            int idx = it*256 + tid;
            int t = idx >> 6, d = idx & 63;
            int du = base + t - 63;
            du = du < -512 ? -512 : (du > 512 ? 512 : du);
            sRel[t*65+d] = rel_emb[(du + 512)*64 + d];
        }
        __syncthreads();

        // ---- S = complex q.k^T (raw sums, scale applied at magnitude) ----
        float sr[4][4] = {}, si[4][4] = {};
        #pragma unroll 8
        for (int d = 0; d < 64; ++d) {
            float qr[4], qi[4], kr[4], ki[4];
            #pragma unroll
            for (int i = 0; i < 4; ++i) { qr[i]=sQr[(4*ti+i)*65+d]; qi[i]=sQi[(4*ti+i)*65+d]; }
            #pragma unroll
            for (int j = 0; j < 4; ++j) { kr[j]=sKr[(4*tj+j)*65+d]; ki[j]=sKi[(4*tj+j)*65+d]; }
            #pragma unroll
            for (int i = 0; i < 4; ++i)
            #pragma unroll
            for (int j = 0; j < 4; ++j) {
                sr[i][j] += qr[i]*kr[j] - qi[i]*ki[j];
                si[i][j] += qr[i]*ki[j] + qi[i]*kr[j];
            }
        }

        // ---- E_r = qr @ rel^T, gather anti-diagonals into sr ----
        {
            float e[4][8] = {};
            #pragma unroll 8
            for (int d = 0; d < 64; ++d) {
                float q4[4], rl[8];
                #pragma unroll
                for (int i = 0; i < 4; ++i) q4[i] = sQr[(4*ti+i)*65+d];
                #pragma unroll
                for (int u = 0; u < 8; ++u) rl[u] = sRel[(8*tj+u)*65+d];
                #pragma unroll
                for (int i = 0; i < 4; ++i)
                #pragma unroll
                for (int u = 0; u < 8; ++u) e[i][u] += q4[i]*rl[u];
            }
            #pragma unroll
            for (int i = 0; i < 4; ++i)
            #pragma unroll
            for (int u = 0; u < 8; ++u) sE[(4*ti+i)*129 + 8*tj+u] = e[i][u];
        }
        __syncthreads();
        #pragma unroll
        for (int i = 0; i < 4; ++i)
        #pragma unroll
        for (int j = 0; j < 4; ++j) {
            int r = 4*ti+i, c = 4*tj+j;
            sr[i][j] += sE[r*129 + (r - c + 63)];
        }
        __syncthreads();
        // ---- E_i = qi @ rel^T ----
        {
            float e[4][8] = {};
            #pragma unroll 8
            for (int d = 0; d < 64; ++d) {
                float q4[4], rl[8];
                #pragma unroll
                for (int i = 0; i < 4; ++i) q4[i] = sQi[(4*ti+i)*65+d];
                #pragma unroll
                for (int u = 0; u < 8; ++u) rl[u] = sRel[(8*tj+u)*65+d];
                #pragma unroll
                for (int i = 0; i < 4; ++i)
                #pragma unroll
                for (int u = 0; u < 8; ++u) e[i][u] += q4[i]*rl[u];
            }
            #pragma unroll
            for (int i = 0; i < 4; ++i)
            #pragma unroll
            for (int u = 0; u < 8; ++u) sE[(4*ti+i)*129 + 8*tj+u] = e[i][u];
        }
        __syncthreads();
        #pragma unroll
        for (int i = 0; i < 4; ++i)
        #pragma unroll
        for (int j = 0; j < 4; ++j) {
            int r = 4*ti+i, c = 4*tj+j;
            si[i][j] += sE[r*129 + (r - c + 63)];
        }

        // ---- magnitude + online softmax ----
        float m_[4][4];
        #pragma unroll
        for (int i = 0; i < 4; ++i) {
            float tmax = -1e30f;
            #pragma unroll
            for (int j = 0; j < 4; ++j) {
                float v = CSCALE * sqrtf(sr[i][j]*sr[i][j] + si[i][j]*si[i][j]);
                m_[i][j] = v;
                tmax = fmaxf(tmax, v);
            }
            sRed[(4*ti+i)*16 + tj] = tmax;
        }
        __syncthreads();
        if (tid < 64) {
            float mOld = rowMax[tid], mx = mOld;
            #pragma unroll
            for (int t = 0; t < 16; ++t) mx = fmaxf(mx, sRed[tid*16+t]);
            alpha[tid] = __expf(mOld - mx);
            rowMax[tid] = mx;
        }
        __syncthreads();
        #pragma unroll
        for (int i = 0; i < 4; ++i) {
            float nm = rowMax[4*ti+i];
            float tsum = 0.f;
            #pragma unroll
            for (int j = 0; j < 4; ++j) {
                float p = __expf(m_[i][j] - nm);
                sP[(4*ti+i)*65 + 4*tj+j] = p;
                tsum += p;
            }
            sRed[(4*ti+i)*16 + tj] = tsum;
        }
        // rescale O accumulators by alpha
        #pragma unroll
        for (int i = 0; i < 4; ++i) {
            float al = alpha[4*ti+i];
            #pragma unroll
            for (int j = 0; j < 4; ++j) { o_r[i][j]*=al; o_i[i][j]*=al; }
        }
        __syncthreads();
        if (tid < 64) {
            float s = 0.f;
            #pragma unroll
            for (int t = 0; t < 16; ++t) s += sRed[tid*16+t];
            rowL[tid] = rowL[tid]*alpha[tid] + s;
        }

        // ---- O += P @ V (real attn, complex V) ----
        #pragma unroll 8
        for (int jj = 0; jj < 64; ++jj) {
            float p4[4], vr4[4], vi4[4];
            #pragma unroll
            for (int i = 0; i < 4; ++i) p4[i] = sP[(4*ti+i)*65 + jj];
            #pragma unroll
            for (int j = 0; j < 4; ++j) { vr4[j]=sVr[jj*65 + 4*tj+j]; vi4[j]=sVi[jj*65 + 4*tj+j]; }
            #pragma unroll
            for (int i = 0; i < 4; ++i)
            #pragma unroll
            for (int j = 0; j < 4; ++j) {
                o_r[i][j] += p4[i]*vr4[j];
                o_i[i][j] += p4[i]*vi4[j];
            }
        }
        __syncthreads();
    }

    // ---- finalize: O /= L, write [b][n][h*64+d] ----
    const int b = bh >> 3, h = bh & 7;
    #pragma unroll
    for (int i = 0; i < 4; ++i) {
        int r = 4*ti + i;
        float inv = 1.0f / rowL[r];
        int n = i0 + r;
        size_t rowbase = ((size_t)b*CN + n)*CINNER + h*64;
        #pragma unroll
        for (int j = 0; j < 4; ++j) {
            g_ar[rowbase + 4*tj+j] = o_r[i][j]*inv;
            g_ai[rowbase + 4*tj+j] = o_i[i][j]*inv;
        }
    }
}

// =====================================================================
// Kernel 3: output complex projection + bias, interleaved float2 output.
// =====================================================================
__global__ __launch_bounds__(256) void k_proj_out(
    const float* __restrict__ wo_r, const float* __restrict__ wo_i,
    const float* __restrict__ bo_r, const float* __restrict__ bo_i,
    float2* __restrict__ out)
{
    __shared__ float Asr[16][65], Asi[16][65], Bsr[16][65], Bsi[16][65];
    const int m0 = blockIdx.x * 64;
    const int c0 = blockIdx.y * 64;
    const int tid = threadIdx.x;
    const int ti = tid >> 4, tj = tid & 15;
    float cr[4][4] = {}, ci[4][4] = {};

    for (int k0 = 0; k0 < CINNER; k0 += 16) {
        #pragma unroll
        for (int it = 0; it < 4; ++it) {
            int idx = it*256 + tid;
            int row = idx >> 4, kk = idx & 15;
            size_t g = (size_t)(m0+row)*CINNER + k0 + kk;
            Asr[kk][row] = g_ar[g];
            Asi[kk][row] = g_ai[g];
        }
        #pragma unroll
        for (int it = 0; it < 4; ++it) {
            int idx = it*256 + tid;
            int kk = idx >> 6, c = idx & 63;
            Bsr[kk][c] = wo_r[(k0+kk)*512 + c0 + c];
            Bsi[kk][c] = wo_i[(k0+kk)*512 + c0 + c];
        }
        __syncthreads();
        #pragma unroll
        for (int kk = 0; kk < 16; ++kk) {
            float ar[4], ai[4], br[4], bi[4];
            #pragma unroll
            for (int i = 0; i < 4; ++i) { ar[i]=Asr[kk][ti*4+i]; ai[i]=Asi[kk][ti*4+i]; }
            #pragma unroll
            for (int j = 0; j < 4; ++j) { br[j]=Bsr[kk][tj*4+j]; bi[j]=Bsi[kk][tj*4+j]; }
            #pragma unroll
            for (int i = 0; i < 4; ++i)
            #pragma unroll
            for (int j = 0; j < 4; ++j) {
                cr[i][j] += ar[i]*br[j] - ai[i]*bi[j];
                ci[i][j] += ai[i]*br[j] + ar[i]*bi[j];
            }
        }
        __syncthreads();
    }
    #pragma unroll
    for (int i = 0; i < 4; ++i) {
        int m = m0 + 4*ti + i;
        #pragma unroll
        for (int j = 0; j < 4; ++j) {
            int cg = c0 + 4*tj + j;
            float r  = cr[i][j] + bo_r[cg];
            float im = ci[i][j] + bo_i[cg];
            out[(size_t)m*512 + cg] = make_float2(r, im);
        }
    }
}

// =====================================================================
extern "C" void kernel_launch(void* const* d_in, const int* in_sizes, int n_in,
                              void* d_out, int out_size)
{
    const float2* x     = (const float2*)d_in[0];
    const float* wq_r   = (const float*)d_in[1];
    const float* wq_i   = (const float*)d_in[2];
    const float* wkv_r  = (const float*)d_in[3];
    const float* wkv_i  = (const float*)d_in[4];
    const float* wo_r   = (const float*)d_in[5];
    const float* wo_i   = (const float*)d_in[6];
    const float* bo_r   = (const float*)d_in[7];
    const float* bo_i   = (const float*)d_in[8];
    const float* rel    = (const float*)d_in[9];

    cudaFuncSetAttribute(k_attn, cudaFuncAttributeMaxDynamicSharedMemorySize,
                         ATTN_SMEM_BYTES);

    k_proj_qkv<<<dim3(64, 24), 256>>>(x, wq_r, wq_i, wkv_r, wkv_i);
    k_attn<<<dim3(32, 16), 256, ATTN_SMEM_BYTES>>>(rel);
    k_proj_out<<<dim3(64, 8), 256>>>(wo_r, wo_i, bo_r, bo_i, (float2*)d_out);
}

// round 3
// speedup vs baseline: 1.0002x; 1.0002x over previous
#include <cuda_runtime.h>
#include <math.h>

// Problem constants
#define CB 4
#define CN 1024
#define CDIM 512
#define CH 8
#define CD 64
#define CINNER 512
#define CBH (CB*CH)          // 32
#define CMTOT (CB*CN)        // 4096
#define CSCALE 0.125f        // 64^-0.5

// ---------------- scratch (allocation-free: __device__ globals) ----------------
__device__ float g_qr[CBH*CN*CD];
__device__ float g_qi[CBH*CN*CD];
__device__ float g_kr[CBH*CN*CD];
__device__ float g_ki[CBH*CN*CD];
__device__ float g_vr[CBH*CN*CD];
__device__ float g_vi[CBH*CN*CD];
__device__ float g_ar[CMTOT*CINNER];   // attention out (real), [b][n][h*64+d]
__device__ float g_ai[CMTOT*CINNER];   // attention out (imag)

// =====================================================================
// Kernel 1: fused complex QKV projection.
//   A = x  [4096 rows, 512 k] complex (float2 interleaved)
//   B = [wq (512 cols) | wkv (1024 cols)] complex
//   outputs scattered to planar q/k/v [bh][n][d]
// =====================================================================
__global__ __launch_bounds__(256) void k_proj_qkv(
    const float2* __restrict__ x,
    const float* __restrict__ wq_r, const float* __restrict__ wq_i,
    const float* __restrict__ wkv_r, const float* __restrict__ wkv_i)
{
    __shared__ float Asr[16][65], Asi[16][65], Bsr[16][65], Bsi[16][65];
    const int m0 = blockIdx.x * 64;
    const int c0 = blockIdx.y * 64;            // complex output col tile (0..1535)
    const int tid = threadIdx.x;
    const int ti = tid >> 4, tj = tid & 15;
    float cr[4][4] = {}, ci[4][4] = {};

    for (int k0 = 0; k0 < CDIM; k0 += 16) {
        #pragma unroll
        for (int it = 0; it < 4; ++it) {
            int idx = it*256 + tid;
            int row = idx >> 4, kk = idx & 15;
            float2 v = x[(size_t)(m0+row)*CDIM + k0 + kk];
            Asr[kk][row] = v.x; Asi[kk][row] = v.y;
        }
        #pragma unroll
        for (int it = 0; it < 4; ++it) {
            int idx = it*256 + tid;
            int kk = idx >> 6, c = idx & 63;
            int cg = c0 + c, krw = k0 + kk;
            float br, bi;
            if (cg < 512) { br = wq_r[krw*512 + cg];          bi = wq_i[krw*512 + cg]; }
            else          { br = wkv_r[krw*1024 + (cg-512)];  bi = wkv_i[krw*1024 + (cg-512)]; }
            Bsr[kk][c] = br; Bsi[kk][c] = bi;
        }
        __syncthreads();
        #pragma unroll
        for (int kk = 0; kk < 16; ++kk) {
            float ar[4], ai[4], br[4], bi[4];
            #pragma unroll
            for (int i = 0; i < 4; ++i) { ar[i]=Asr[kk][ti*4+i]; ai[i]=Asi[kk][ti*4+i]; }
            #pragma unroll
            for (int j = 0; j < 4; ++j) { br[j]=Bsr[kk][tj*4+j]; bi[j]=Bsi[kk][tj*4+j]; }
            #pragma unroll
            for (int i = 0; i < 4; ++i)
            #pragma unroll
            for (int j = 0; j < 4; ++j) {
                cr[i][j] += ar[i]*br[j] - ai[i]*bi[j];
                ci[i][j] += ai[i]*br[j] + ar[i]*bi[j];
            }
        }
        __syncthreads();
    }
    #pragma unroll
    for (int i = 0; i < 4; ++i) {
        int m = m0 + ti*4 + i;
        int b = m >> 10, n = m & 1023;
        #pragma unroll
        for (int j = 0; j < 4; ++j) {
            int cg = c0 + tj*4 + j;
            float r = cr[i][j], im = ci[i][j];
            int local = cg & 511;              // works for all three ranges
            int h = local >> 6, d = local & 63;
            size_t o = (((size_t)b*CH + h)*CN + n)*CD + d;
            if (cg < 512)       { g_qr[o] = r; g_qi[o] = im; }
            else if (cg < 1024) { g_kr[o] = r; g_ki[o] = im; }
            else                { g_vr[o] = r; g_vi[o] = im; }
        }
    }
}

// =====================================================================
// Kernel 2: fused complex attention with magnitude online-softmax.
// Per block: one (b,h) and one 64-row query tile; loop over 16 key tiles.
// Rel-position handled per tile-pair via E[ii,t]=q[ii]·rel_row[t] GEMM +
// anti-diagonal gather (t = ii-jj+63).
// =====================================================================
#define ATTN_SMEM_FLOATS 46912
#define ATTN_SMEM_BYTES  (ATTN_SMEM_FLOATS*4)

__global__ __launch_bounds__(256) void k_attn(const float* __restrict__ rel_emb)
{
    extern __shared__ float sm[];
    float* sQr   = sm;                 // 64*65
    float* sQi   = sQr + 4160;
    float* sKr   = sQi + 4160;
    float* sKi   = sKr + 4160;
    float* sVr   = sKi + 4160;
    float* sVi   = sVr + 4160;
    float* sRel  = sVi + 4160;         // 128*65
    float* sE    = sRel + 8320;        // 64*129
    float* sP    = sE + 8256;          // 64*65
    float* rowMax= sP + 4160;          // 64
    float* rowL  = rowMax + 64;        // 64
    float* alpha = rowL + 64;          // 64
    float* sRed  = alpha + 64;         // 64*16

    const int bh = blockIdx.x;         // 0..31
    const int i0 = blockIdx.y * 64;    // query tile start
    const int tid = threadIdx.x;
    const int ti = tid >> 4, tj = tid & 15;

    #pragma unroll
    for (int it = 0; it < 16; ++it) {
        int idx = it*256 + tid;
        int row = idx >> 6, d = idx & 63;
        size_t g = ((size_t)bh*CN + i0 + row)*CD + d;
        sQr[row*65 + d] = g_qr[g];
        sQi[row*65 + d] = g_qi[g];
    }
    if (tid < 64) { rowMax[tid] = -1e30f; rowL[tid] = 0.f; }
    float o_r[4][4] = {}, o_i[4][4] = {};
    __syncthreads();

    for (int jt = 0; jt < 16; ++jt) {
        const int j0 = jt * 64;
        #pragma unroll
        for (int it = 0; it < 16; ++it) {
            int idx = it*256 + tid;
            int row = idx >> 6, d = idx & 63;
            size_t g = ((size_t)bh*CN + j0 + row)*CD + d;
            sKr[row*65+d] = g_kr[g];
            sKi[row*65+d] = g_ki[g];
            sVr[row*65+d] = g_vr[g];
            sVi[row*65+d] = g_vi[g];
        }
        const int base = i0 - j0;
        #pragma unroll
        for (int it = 0; it < 32; ++it) {
            int idx = it*256 + tid;
            int t = idx >> 6, d = idx & 63;
            int du = base + t - 63;
            du = du < -512 ? -512 : (du > 512 ? 512 : du);
            sRel[t*65+d] = rel_emb[(du + 512)*64 + d];
        }
        __syncthreads();

        // ---- S = complex q.k^T (raw sums, scale applied at magnitude) ----
        float sr[4][4] = {}, si[4][4] = {};
        #pragma unroll 8
        for (int d = 0; d < 64; ++d) {
            float qr[4], qi[4], kr[4], ki[4];
            #pragma unroll
            for (int i = 0; i < 4; ++i) { qr[i]=sQr[(4*ti+i)*65+d]; qi[i]=sQi[(4*ti+i)*65+d]; }
            #pragma unroll
            for (int j = 0; j < 4; ++j) { kr[j]=sKr[(4*tj+j)*65+d]; ki[j]=sKi[(4*tj+j)*65+d]; }
            #pragma unroll
            for (int i = 0; i < 4; ++i)
            #pragma unroll
            for (int j = 0; j < 4; ++j) {
                sr[i][j] += qr[i]*kr[j] - qi[i]*ki[j];
                si[i][j] += qr[i]*ki[j] + qi[i]*kr[j];
            }
        }

        // ---- E_r = qr @ rel^T, gather anti-diagonals into sr ----
        {
            float e[4][8] = {};
            #pragma unroll 8
            for (int d = 0; d < 64; ++d) {
                float q4[4], rl[8];
                #pragma unroll
                for (int i = 0; i < 4; ++i) q4[i] = sQr[(4*ti+i)*65+d];
                #pragma unroll
                for (int u = 0; u < 8; ++u) rl[u] = sRel[(8*tj+u)*65+d];
                #pragma unroll
                for (int i = 0; i < 4; ++i)
                #pragma unroll
                for (int u = 0; u < 8; ++u) e[i][u] += q4[i]*rl[u];
            }
            #pragma unroll
            for (int i = 0; i < 4; ++i)
            #pragma unroll
            for (int u = 0; u < 8; ++u) sE[(4*ti+i)*129 + 8*tj+u] = e[i][u];
        }
        __syncthreads();
        #pragma unroll
        for (int i = 0; i < 4; ++i)
        #pragma unroll
        for (int j = 0; j < 4; ++j) {
            int r = 4*ti+i, c = 4*tj+j;
            sr[i][j] += sE[r*129 + (r - c + 63)];
        }
        __syncthreads();
        // ---- E_i = qi @ rel^T ----
        {
            float e[4][8] = {};
            #pragma unroll 8
            for (int d = 0; d < 64; ++d) {
                float q4[4], rl[8];
                #pragma unroll
                for (int i = 0; i < 4; ++i) q4[i] = sQi[(4*ti+i)*65+d];
                #pragma unroll
                for (int u = 0; u < 8; ++u) rl[u] = sRel[(8*tj+u)*65+d];
                #pragma unroll
                for (int i = 0; i < 4; ++i)
                #pragma unroll
                for (int u = 0; u < 8; ++u) e[i][u] += q4[i]*rl[u];
            }
            #pragma unroll
            for (int i = 0; i < 4; ++i)
            #pragma unroll
            for (int u = 0; u < 8; ++u) sE[(4*ti+i)*129 + 8*tj+u] = e[i][u];
        }
        __syncthreads();
        #pragma unroll
        for (int i = 0; i < 4; ++i)
        #pragma unroll
        for (int j = 0; j < 4; ++j) {
            int r = 4*ti+i, c = 4*tj+j;
            si[i][j] += sE[r*129 + (r - c + 63)];
        }

        // ---- magnitude + online softmax ----
        float m_[4][4];
        #pragma unroll
        for (int i = 0; i < 4; ++i) {
            float tmax = -1e30f;
            #pragma unroll
            for (int j = 0; j < 4; ++j) {
                float v = CSCALE * sqrtf(sr[i][j]*sr[i][j] + si[i][j]*si[i][j]);
                m_[i][j] = v;
                tmax = fmaxf(tmax, v);
            }
            sRed[(4*ti+i)*16 + tj] = tmax;
        }
        __syncthreads();
        if (tid < 64) {
            float mOld = rowMax[tid], mx = mOld;
            #pragma unroll
            for (int t = 0; t < 16; ++t) mx = fmaxf(mx, sRed[tid*16+t]);
            alpha[tid] = __expf(mOld - mx);
            rowMax[tid] = mx;
        }
        __syncthreads();
        #pragma unroll
        for (int i = 0; i < 4; ++i) {
            float nm = rowMax[4*ti+i];
            float tsum = 0.f;
            #pragma unroll
            for (int j = 0; j < 4; ++j) {
                float p = __expf(m_[i][j] - nm);
                sP[(4*ti+i)*65 + 4*tj+j] = p;
                tsum += p;
            }
            sRed[(4*ti+i)*16 + tj] = tsum;
        }
        // rescale O accumulators by alpha
        #pragma unroll
        for (int i = 0; i < 4; ++i) {
            float al = alpha[4*ti+i];
            #pragma unroll
            for (int j = 0; j < 4; ++j) { o_r[i][j]*=al; o_i[i][j]*=al; }
        }
        __syncthreads();
        if (tid < 64) {
            float s = 0.f;
            #pragma unroll
            for (int t = 0; t < 16; ++t) s += sRed[tid*16+t];
            rowL[tid] = rowL[tid]*alpha[tid] + s;
        }

        // ---- O += P @ V (real attn, complex V) ----
        #pragma unroll 8
        for (int jj = 0; jj < 64; ++jj) {
            float p4[4], vr4[4], vi4[4];
            #pragma unroll
            for (int i = 0; i < 4; ++i) p4[i] = sP[(4*ti+i)*65 + jj];
            #pragma unroll
            for (int j = 0; j < 4; ++j) { vr4[j]=sVr[jj*65 + 4*tj+j]; vi4[j]=sVi[jj*65 + 4*tj+j]; }
            #pragma unroll
            for (int i = 0; i < 4; ++i)
            #pragma unroll
            for (int j = 0; j < 4; ++j) {
                o_r[i][j] += p4[i]*vr4[j];
                o_i[i][j] += p4[i]*vi4[j];
            }
        }
        __syncthreads();
    }

    // ---- finalize: O /= L, write [b][n][h*64+d] ----
    const int b = bh >> 3, h = bh & 7;
    #pragma unroll
    for (int i = 0; i < 4; ++i) {
        int r = 4*ti + i;
        float inv = 1.0f / rowL[r];
        int n = i0 + r;
        size_t rowbase = ((size_t)b*CN + n)*CINNER + h*64;
        #pragma unroll
        for (int j = 0; j < 4; ++j) {
            g_ar[rowbase + 4*tj+j] = o_r[i][j]*inv;
            g_ai[rowbase + 4*tj+j] = o_i[i][j]*inv;
        }
    }
}

// =====================================================================
// Kernel 3: output complex projection + bias, interleaved float2 output.
// =====================================================================
__global__ __launch_bounds__(256) void k_proj_out(
    const float* __restrict__ wo_r, const float* __restrict__ wo_i,
    const float* __restrict__ bo_r, const float* __restrict__ bo_i,
    float2* __restrict__ out)
{
    __shared__ float Asr[16][65], Asi[16][65], Bsr[16][65], Bsi[16][65];
    const int m0 = blockIdx.x * 64;
    const int c0 = blockIdx.y * 64;
    const int tid = threadIdx.x;
    const int ti = tid >> 4, tj = tid & 15;
    float cr[4][4] = {}, ci[4][4] = {};

    for (int k0 = 0; k0 < CINNER; k0 += 16) {
        #pragma unroll
        for (int it = 0; it < 4; ++it) {
            int idx = it*256 + tid;
            int row = idx >> 4, kk = idx & 15;
            size_t g = (size_t)(m0+row)*CINNER + k0 + kk;
            Asr[kk][row] = g_ar[g];
            Asi[kk][row] = g_ai[g];
        }
        #pragma unroll
        for (int it = 0; it < 4; ++it) {
            int idx = it*256 + tid;
            int kk = idx >> 6, c = idx & 63;
            Bsr[kk][c] = wo_r[(k0+kk)*512 + c0 + c];
            Bsi[kk][c] = wo_i[(k0+kk)*512 + c0 + c];
        }
        __syncthreads();
        #pragma unroll
        for (int kk = 0; kk < 16; ++kk) {
            float ar[4], ai[4], br[4], bi[4];
            #pragma unroll
            for (int i = 0; i < 4; ++i) { ar[i]=Asr[kk][ti*4+i]; ai[i]=Asi[kk][ti*4+i]; }
            #pragma unroll
            for (int j = 0; j < 4; ++j) { br[j]=Bsr[kk][tj*4+j]; bi[j]=Bsi[kk][tj*4+j]; }
            #pragma unroll
            for (int i = 0; i < 4; ++i)
            #pragma unroll
            for (int j = 0; j < 4; ++j) {
                cr[i][j] += ar[i]*br[j] - ai[i]*bi[j];
                ci[i][j] += ai[i]*br[j] + ar[i]*bi[j];
            }
        }
        __syncthreads();
    }
    #pragma unroll
    for (int i = 0; i < 4; ++i) {
        int m = m0 + 4*ti + i;
        #pragma unroll
        for (int j = 0; j < 4; ++j) {
            int cg = c0 + 4*tj + j;
            float r  = cr[i][j] + bo_r[cg];
            float im = ci[i][j] + bo_i[cg];
            out[(size_t)m*512 + cg] = make_float2(r, im);
        }
    }
}

// =====================================================================
extern "C" void kernel_launch(void* const* d_in, const int* in_sizes, int n_in,
                              void* d_out, int out_size)
{
    const float2* x     = (const float2*)d_in[0];
    const float* wq_r   = (const float*)d_in[1];
    const float* wq_i   = (const float*)d_in[2];
    const float* wkv_r  = (const float*)d_in[3];
    const float* wkv_i  = (const float*)d_in[4];
    const float* wo_r   = (const float*)d_in[5];
    const float* wo_i   = (const float*)d_in[6];
    const float* bo_r   = (const float*)d_in[7];
    const float* bo_i   = (const float*)d_in[8];
    const float* rel    = (const float*)d_in[9];

    cudaFuncSetAttribute(k_attn, cudaFuncAttributeMaxDynamicSharedMemorySize,
                         ATTN_SMEM_BYTES);

    k_proj_qkv<<<dim3(64, 24), 256>>>(x, wq_r, wq_i, wkv_r, wkv_i);
    k_attn<<<dim3(32, 16), 256, ATTN_SMEM_BYTES>>>(rel);
    k_proj_out<<<dim3(64, 8), 256>>>(wo_r, wo_i, bo_r, bo_i, (float2*)d_out);
}

// round 6
// speedup vs baseline: 2.8776x; 2.8770x over previous
#include <cuda_runtime.h>
#include <cuda_bf16.h>
#include <cuda_fp16.h>
#include <stdint.h>
#include <math.h>

typedef __nv_bfloat16 bf16;

// ---------------- scratch (__device__ globals; allocation-free) ----------------
__device__ bf16   gAq[(size_t)4096*3072];
__device__ bf16   gBq[(size_t)3072*3072];
__device__ float  gCq[(size_t)4096*3072];
__device__ bf16   gAs[(size_t)32*1024*384];
__device__ bf16   gBs[(size_t)32*2048*384];
__device__ float  gS [(size_t)32*1024*2048];
__device__ bf16   gAe[(size_t)32*2048*64];
__device__ bf16   gBe[(size_t)1152*64];        // rows >=1025 stay zero
__device__ __half gR [(size_t)32*2048*1152];
__device__ bf16   gP [(size_t)32*1024*3072];
__device__ bf16   gBpv[(size_t)32*128*3072];
__device__ float  gCpv[(size_t)32*1024*128];
__device__ bf16   gAo[(size_t)4096*3072];
__device__ bf16   gBo[(size_t)1024*3072];
__device__ float  gCo[(size_t)4096*1024];

// ---------------- helpers ----------------
__device__ __forceinline__ uint32_t smem_u32(const void* p){
    uint32_t a;
    asm("{ .reg .u64 t; cvta.to.shared.u64 t, %1; cvt.u32.u64 %0, t; }" : "=r"(a) : "l"(p));
    return a;
}
__device__ __forceinline__ void bsplit(float v, bf16& h, bf16& l){
    h = __float2bfloat16(v);
    l = __float2bfloat16(v - __bfloat162float(h));
}
__device__ __forceinline__ void ldm_x4(uint32_t* r, uint32_t addr){
    asm volatile("ldmatrix.sync.aligned.m8n8.x4.shared.b16 {%0,%1,%2,%3}, [%4];"
                 : "=r"(r[0]), "=r"(r[1]), "=r"(r[2]), "=r"(r[3]) : "r"(addr));
}
__device__ __forceinline__ void mma_bf16(float* c, const uint32_t* a, const uint32_t* b){
    asm volatile(
        "mma.sync.aligned.m16n8k16.row.col.f32.bf16.bf16.f32 "
        "{%0,%1,%2,%3}, {%4,%5,%6,%7}, {%8,%9}, {%0,%1,%2,%3};"
        : "+f"(c[0]), "+f"(c[1]), "+f"(c[2]), "+f"(c[3])
        : "r"(a[0]), "r"(a[1]), "r"(a[2]), "r"(a[3]), "r"(b[0]), "r"(b[1]));
}

// =====================================================================
// Generic batched GEMM: C[z][M][N] = A[z][M][K] * B[z][N][K]^T
// bf16 in (K-major), fp32 accum via HMMA m16n8k16; C fp32 or fp16.
// Tile 128x128, K-chunk 64 staged in SW128-swizzled smem.
// =====================================================================
__global__ __launch_bounds__(256) void k_gemm(
    const bf16* __restrict__ A, const bf16* __restrict__ B, void* __restrict__ Cv,
    int K, int ldc, long long sA, long long sB, long long sC, int outHalf)
{
    __shared__ __align__(1024) char smA[16384];
    __shared__ __align__(1024) char smB[16384];
    const uint32_t aA = smem_u32(smA), aB = smem_u32(smB);
    const int tid = threadIdx.x, wid = tid >> 5, lid = tid & 31;
    const int wm = wid & 1, wn = wid >> 1;           // 2 x 4 warp grid
    const int m0 = blockIdx.x << 7, n0 = blockIdx.y << 7, z = blockIdx.z;
    A += (size_t)z * (size_t)sA;
    B += (size_t)z * (size_t)sB;

    float acc[4][4][4];
    #pragma unroll
    for (int i = 0; i < 4; ++i)
    #pragma unroll
    for (int j = 0; j < 4; ++j)
    #pragma unroll
    for (int k = 0; k < 4; ++k) acc[i][j][k] = 0.f;

    // precomputed ldmatrix addressing pieces
    // A: row = wm*64 + mt*16 + (lid&15); k-unit(16B) = s*2 + (lid>>4)
    const int arow = wm*64 + (lid & 15);
    const uint32_t ahi = (uint32_t)(lid >> 4) << 4;           // 0 or 16 bytes
    // B: row = wn*32 + (2p + (g>>1))*8 + (lid&7); unit = s*2 + (g&1)
    const int g = lid >> 3;
    const int brow = wn*32 + ((g >> 1) << 3) + (lid & 7);
    const uint32_t bhi = (uint32_t)(g & 1) << 4;

    const int nch = K >> 6, kq = K >> 3;

    for (int c = 0; c < nch; ++c){
        const uint4* a4 = (const uint4*)(A + (size_t)m0 * K) + c * 8;
        const uint4* b4 = (const uint4*)(B + (size_t)n0 * K) + c * 8;
        #pragma unroll
        for (int it = 0; it < 4; ++it){
            int idx = it * 256 + tid;
            int r = idx >> 3, q = idx & 7;
            uint32_t off = (uint32_t)((r << 7) | (q << 4));
            uint32_t sw = off ^ ((off >> 3) & 0x70);
            *(uint4*)(smA + sw) = a4[(size_t)r * kq + q];
            *(uint4*)(smB + sw) = b4[(size_t)r * kq + q];
        }
        __syncthreads();

        #pragma unroll
        for (int s = 0; s < 4; ++s){
            const uint32_t slo = (uint32_t)s << 5;            // s*32 bytes
            uint32_t af[4][4], bf[4][2];
            #pragma unroll
            for (int mt = 0; mt < 4; ++mt){
                int row = arow + mt*16;
                uint32_t base = (uint32_t)(row << 7);
                uint32_t addr = aA + base + ((slo + ahi) ^ (((uint32_t)(row & 7)) << 4));
                ldm_x4(af[mt], addr);
            }
            #pragma unroll
            for (int p = 0; p < 2; ++p){
                int row = brow + p*16;
                uint32_t base = (uint32_t)(row << 7);
                uint32_t addr = aB + base + ((slo + bhi) ^ (((uint32_t)(row & 7)) << 4));
                uint32_t rr[4];
                ldm_x4(rr, addr);
                bf[2*p][0] = rr[0]; bf[2*p][1] = rr[1];
                bf[2*p+1][0] = rr[2]; bf[2*p+1][1] = rr[3];
            }
            #pragma unroll
            for (int mt = 0; mt < 4; ++mt)
            #pragma unroll
            for (int nt = 0; nt < 4; ++nt)
                mma_bf16(acc[mt][nt], af[mt], bf[nt]);
        }
        __syncthreads();
    }

    // epilogue: thread holds c0,c1 @ (row0, col), c2,c3 @ (row0+8, col)
    const int rbase = m0 + wm*64 + (lid >> 2);
    const int cbase = n0 + wn*32 + (lid & 3)*2;
    if (!outHalf){
        float* C = (float*)Cv + (size_t)z * sC;
        #pragma unroll
        for (int mt = 0; mt < 4; ++mt)
        #pragma unroll
        for (int nt = 0; nt < 4; ++nt){
            int r0 = rbase + mt*16, cc = cbase + nt*8;
            *(float2*)(C + (size_t)r0 * ldc + cc)       = make_float2(acc[mt][nt][0], acc[mt][nt][1]);
            *(float2*)(C + (size_t)(r0+8) * ldc + cc)   = make_float2(acc[mt][nt][2], acc[mt][nt][3]);
        }
    } else {
        __half* C = (__half*)Cv + (size_t)z * sC;
        #pragma unroll
        for (int mt = 0; mt < 4; ++mt)
        #pragma unroll
        for (int nt = 0; nt < 4; ++nt){
            int r0 = rbase + mt*16, cc = cbase + nt*8;
            *(__half2*)(C + (size_t)r0 * ldc + cc)     = __floats2half2_rn(acc[mt][nt][0], acc[mt][nt][1]);
            *(__half2*)(C + (size_t)(r0+8) * ldc + cc) = __floats2half2_rn(acc[mt][nt][2], acc[mt][nt][3]);
        }
    }
}

// =====================================================================
// Prep / elementwise kernels
// =====================================================================
__global__ void k_prep_xA(const float2* __restrict__ x){
    int idx = blockIdx.x * 256 + threadIdx.x;      // 4096*1024
    int m = idx >> 10, ka = idx & 1023;
    float v = (ka < 512) ? x[(size_t)m*512 + ka].x : x[(size_t)m*512 + ka - 512].y;
    bf16 h, l; bsplit(v, h, l);
    size_t b = (size_t)m * 3072;
    gAq[b+ka] = h; gAq[b+1024+ka] = l; gAq[b+2048+ka] = h;
}

__global__ void k_prep_qkvB(const float* __restrict__ wq_r, const float* __restrict__ wq_i,
                            const float* __restrict__ wkv_r, const float* __restrict__ wkv_i){
    int idx = blockIdx.x * 256 + threadIdx.x;      // 3072*1024
    int n = idx >> 10, k = idx & 1023;
    int ka = k & 511, isb = k >> 9;
    int im = n >= 1536;
    int c = im ? n - 1536 : n;
    const float* Wr = (c < 512) ? wq_r : wkv_r;
    const float* Wi = (c < 512) ? wq_i : wkv_i;
    int cc = (c < 512) ? c : c - 512;
    int ldw = (c < 512) ? 512 : 1024;
    float wr = Wr[(size_t)ka*ldw + cc], wi = Wi[(size_t)ka*ldw + cc];
    float v = im ? (isb ? wr : wi) : (isb ? -wi : wr);
    bf16 h, l; bsplit(v, h, l);
    size_t b = (size_t)n * 3072;
    gBq[b+k] = h; gBq[b+1024+k] = h; gBq[b+2048+k] = l;
}

__global__ void k_prep_rel(const float* __restrict__ rel){
    int idx = blockIdx.x * 256 + threadIdx.x;
    if (idx < 1025*64) gBe[idx] = __float2bfloat16(rel[idx]);
}

__global__ __launch_bounds__(256) void k_prep_attn(){
    __shared__ float sVr[64][65], sVi[64][65];
    const int bh = blockIdx.x, n0 = blockIdx.y << 6;
    const int b = bh >> 3, h = bh & 7;
    const int tid = threadIdx.x;
    const int dl = tid & 63;
    #pragma unroll
    for (int p = 0; p < 16; ++p){
        int nl = (p << 2) + (tid >> 6);
        int n = n0 + nl;
        size_t mrow = ((size_t)b*1024 + n) * 3072;
        int hd = h*64 + dl;
        float qr = gCq[mrow + hd],        qi = gCq[mrow + 1536 + hd];
        float kr = gCq[mrow + 512 + hd],  ki = gCq[mrow + 2048 + hd];
        float vr = gCq[mrow + 1024 + hd], vi = gCq[mrow + 2560 + hd];
        bf16 qh, ql;  bsplit(qr, qh, ql);
        bf16 ih, il;  bsplit(qi, ih, il);
        size_t ab = ((size_t)bh*1024 + n) * 384;
        gAs[ab+dl] = qh;     gAs[ab+128+dl] = ql;  gAs[ab+256+dl] = qh;
        gAs[ab+64+dl] = ih;  gAs[ab+192+dl] = il;  gAs[ab+320+dl] = ih;
        bf16 kh, kl;  bsplit(kr, kh, kl);
        bf16 nh, nl2; bsplit(-ki, nh, nl2);
        size_t bb = ((size_t)bh*2048 + n) * 384;
        gBs[bb+dl] = kh;     gBs[bb+128+dl] = kh;  gBs[bb+256+dl] = kl;
        gBs[bb+64+dl] = nh;  gBs[bb+192+dl] = nh;  gBs[bb+320+dl] = nl2;
        bf16 kih, kil; bsplit(ki, kih, kil);
        size_t b2 = ((size_t)bh*2048 + 1024 + n) * 384;
        gBs[b2+dl] = kih;    gBs[b2+128+dl] = kih; gBs[b2+256+dl] = kil;
        gBs[b2+64+dl] = kh;  gBs[b2+192+dl] = kh;  gBs[b2+320+dl] = kl;
        gAe[((size_t)bh*2048 + n)*64 + dl] = __float2bfloat16(qr);
        gAe[((size_t)bh*2048 + 1024 + n)*64 + dl] = __float2bfloat16(qi);
        sVr[nl][dl] = vr; sVi[nl][dl] = vi;
    }
    __syncthreads();
    #pragma unroll
    for (int p = 0; p < 16; ++p){
        int d = (p << 2) + (tid >> 6);
        int n_ = tid & 63;
        float vr = sVr[n_][d], vi = sVi[n_][d];
        bf16 h1, l1; bsplit(vr, h1, l1);
        bf16 h2, l2; bsplit(vi, h2, l2);
        size_t r1 = ((size_t)bh*128 + d)      * 3072 + n0 + n_;
        size_t r2 = ((size_t)bh*128 + 64 + d) * 3072 + n0 + n_;
        gBpv[r1] = h1; gBpv[r1+1024] = h1; gBpv[r1+2048] = l1;
        gBpv[r2] = h2; gBpv[r2+1024] = h2; gBpv[r2+2048] = l2;
    }
}

__global__ __launch_bounds__(256) void k_softmax(){
    int rowid = blockIdx.x * 8 + (threadIdx.x >> 5);
    int lane = threadIdx.x & 31;
    int bh = rowid >> 10, i = rowid & 1023;
    const float* S = gS + ((size_t)bh*1024 + i) * 2048;
    const __half* Rr = gR + ((size_t)bh*2048 + i) * 1152;
    const __half* Ri = gR + ((size_t)bh*2048 + 1024 + i) * 1152;
    float mv[32], mx = -1e30f;
    #pragma unroll
    for (int t = 0; t < 32; ++t){
        int j = t*32 + lane;
        int u = i - j; u = u < -512 ? -512 : (u > 512 ? 512 : u); u += 512;
        float sr = S[j]        + __half2float(Rr[u]);
        float si = S[1024 + j] + __half2float(Ri[u]);
        float m = 0.125f * sqrtf(sr*sr + si*si);
        mv[t] = m; mx = fmaxf(mx, m);
    }
    #pragma unroll
    for (int o = 16; o > 0; o >>= 1) mx = fmaxf(mx, __shfl_xor_sync(0xffffffffu, mx, o));
    float s = 0.f;
    #pragma unroll
    for (int t = 0; t < 32; ++t){ float e = __expf(mv[t] - mx); mv[t] = e; s += e; }
    #pragma unroll
    for (int o = 16; o > 0; o >>= 1) s += __shfl_xor_sync(0xffffffffu, s, o);
    float inv = 1.f / s;
    size_t pb = ((size_t)bh*1024 + i) * 3072;
    #pragma unroll
    for (int t = 0; t < 32; ++t){
        int j = t*32 + lane;
        bf16 h, l; bsplit(mv[t] * inv, h, l);
        gP[pb+j] = h; gP[pb+1024+j] = l; gP[pb+2048+j] = h;
    }
}

__global__ void k_prep_outA(){
    int idx = blockIdx.x * 256 + threadIdx.x;   // 4096*1024
    int m = idx >> 10, e = idx & 1023;
    int b = m >> 10, n = m & 1023;
    int eh = e & 511;
    int h = eh >> 6, d = eh & 63;
    float v = gCpv[(((size_t)(b*8 + h))*1024 + n)*128 + ((e >> 9) ? 64 : 0) + d];
    bf16 hh, ll; bsplit(v, hh, ll);
    size_t ab = (size_t)m * 3072;
    gAo[ab+e] = hh; gAo[ab+1024+e] = ll; gAo[ab+2048+e] = hh;
}

__global__ void k_prep_outB(const float* __restrict__ wo_r, const float* __restrict__ wo_i){
    int idx = blockIdx.x * 256 + threadIdx.x;   // 1024*1024
    int n = idx >> 10, k = idx & 1023;
    int c = n & 511, ka = k & 511;
    float wr = wo_r[(size_t)ka*512 + c], wi = wo_i[(size_t)ka*512 + c];
    float v = (n < 512) ? ((k < 512) ? wr : -wi) : ((k < 512) ? wi : wr);
    bf16 h, l; bsplit(v, h, l);
    size_t bb = (size_t)n * 3072;
    gBo[bb+k] = h; gBo[bb+1024+k] = h; gBo[bb+2048+k] = l;
}

__global__ void k_final(const float* __restrict__ bo_r, const float* __restrict__ bo_i,
                        float2* __restrict__ out){
    int idx = blockIdx.x * 256 + threadIdx.x;   // 4096*512
    int m = idx >> 9, c = idx & 511;
    out[(size_t)m*512 + c] = make_float2(gCo[(size_t)m*1024 + c]       + bo_r[c],
                                         gCo[(size_t)m*1024 + 512 + c] + bo_i[c]);
}

// =====================================================================
extern "C" void kernel_launch(void* const* d_in, const int* in_sizes, int n_in,
                              void* d_out, int out_size)
{
    const float2* x    = (const float2*)d_in[0];
    const float* wq_r  = (const float*)d_in[1];
    const float* wq_i  = (const float*)d_in[2];
    const float* wkv_r = (const float*)d_in[3];
    const float* wkv_i = (const float*)d_in[4];
    const float* wo_r  = (const float*)d_in[5];
    const float* wo_i  = (const float*)d_in[6];
    const float* bo_r  = (const float*)d_in[7];
    const float* bo_i  = (const float*)d_in[8];
    const float* rel   = (const float*)d_in[9];

    void *pAq,*pBq,*pCq,*pAs,*pBs,*pS,*pAe,*pBe,*pR,*pP,*pBpv,*pCpv,*pAo,*pBo,*pCo;
    cudaGetSymbolAddress(&pAq, gAq);   cudaGetSymbolAddress(&pBq, gBq);
    cudaGetSymbolAddress(&pCq, gCq);   cudaGetSymbolAddress(&pAs, gAs);
    cudaGetSymbolAddress(&pBs, gBs);   cudaGetSymbolAddress(&pS,  gS);
    cudaGetSymbolAddress(&pAe, gAe);   cudaGetSymbolAddress(&pBe, gBe);
    cudaGetSymbolAddress(&pR,  gR);    cudaGetSymbolAddress(&pP,  gP);
    cudaGetSymbolAddress(&pBpv,gBpv);  cudaGetSymbolAddress(&pCpv,gCpv);
    cudaGetSymbolAddress(&pAo, gAo);   cudaGetSymbolAddress(&pBo, gBo);
    cudaGetSymbolAddress(&pCo, gCo);

    k_prep_xA  <<<16384, 256>>>(x);
    k_prep_qkvB<<<12288, 256>>>(wq_r, wq_i, wkv_r, wkv_i);
    k_prep_rel <<<257, 256>>>(rel);
    k_prep_outB<<<4096, 256>>>(wo_r, wo_i);

    // QKV: C[4096,3072] = A[4096,3072] * B[3072,3072]^T
    k_gemm<<<dim3(32,24,1), 256>>>((bf16*)pAq, (bf16*)pBq, pCq,
        3072, 3072, 0LL, 0LL, 0LL, 0);
    k_prep_attn<<<dim3(32,16), 256>>>();
    // S: per bh, [1024,2048] = A[1024,384]*B[2048,384]^T
    k_gemm<<<dim3(8,16,32), 256>>>((bf16*)pAs, (bf16*)pBs, pS,
        384, 2048, 1024LL*384, 2048LL*384, 1024LL*2048, 0);
    // REL: per bh, [2048,1152] = A[2048,64]*B[1152,64]^T (B broadcast), fp16 out
    k_gemm<<<dim3(16,9,32), 256>>>((bf16*)pAe, (bf16*)pBe, pR,
        64, 1152, 2048LL*64, 0LL, 2048LL*1152, 1);
    k_softmax<<<4096, 256>>>();
    // PV: per bh, [1024,128] = P[1024,3072]*V[128,3072]^T
    k_gemm<<<dim3(8,1,32), 256>>>((bf16*)pP, (bf16*)pBpv, pCpv,
        3072, 128, 1024LL*3072, 128LL*3072, 1024LL*128, 0);
    k_prep_outA<<<16384, 256>>>();
    // OUT: [4096,1024] = A[4096,3072]*B[1024,3072]^T
    k_gemm<<<dim3(32,8,1), 256>>>((bf16*)pAo, (bf16*)pBo, pCo,
        3072, 1024, 0LL, 0LL, 0LL, 0);
    k_final<<<8192, 256>>>(bo_r, bo_i, (float2*)d_out);
}

// round 8
// speedup vs baseline: 3.7084x; 1.2887x over previous
#include <cuda_runtime.h>
#include <cuda_bf16.h>
#include <cuda_fp16.h>
#include <stdint.h>
#include <math.h>

// ---------------- scratch (__device__ globals; allocation-free) ----------------
__device__ __half gAq[(size_t)4096*2048];
__device__ __half gBq[(size_t)3072*2048];
__device__ float  gCq[(size_t)4096*3072];
__device__ __half gAs[(size_t)32*1024*256];
__device__ __half gBs[(size_t)32*2048*256];
__device__ __half gS [(size_t)32*1024*2048];
__device__ __half gAe[(size_t)32*2048*64];
__device__ __half gBe[(size_t)1152*64];        // rows >=1025 stay zero
__device__ __half gR [(size_t)32*2048*1152];
__device__ __half gP [(size_t)32*1024*2048];
__device__ __half gBpv[(size_t)32*128*2048];
__device__ float  gCpv[(size_t)32*1024*128];
__device__ __half gAo[(size_t)4096*2048];
__device__ __half gBo[(size_t)1024*2048];
__device__ float  gCo[(size_t)4096*1024];

// ---------------- helpers ----------------
__device__ __forceinline__ uint32_t smem_u32(const void* p){
    uint32_t a;
    asm("{ .reg .u64 t; cvta.to.shared.u64 t, %1; cvt.u32.u64 %0, t; }" : "=r"(a) : "l"(p));
    return a;
}
__device__ __forceinline__ void hsplit(float v, __half& h, __half& l){
    h = __float2half_rn(v);
    l = __float2half_rn(v - __half2float(h));
}
__device__ __forceinline__ void ldm_x4(uint32_t* r, uint32_t addr){
    asm volatile("ldmatrix.sync.aligned.m8n8.x4.shared.b16 {%0,%1,%2,%3}, [%4];"
                 : "=r"(r[0]), "=r"(r[1]), "=r"(r[2]), "=r"(r[3]) : "r"(addr));
}
__device__ __forceinline__ void mma_f16(float* c, const uint32_t* a, const uint32_t* b){
    asm volatile(
        "mma.sync.aligned.m16n8k16.row.col.f32.f16.f16.f32 "
        "{%0,%1,%2,%3}, {%4,%5,%6,%7}, {%8,%9}, {%0,%1,%2,%3};"
        : "+f"(c[0]), "+f"(c[1]), "+f"(c[2]), "+f"(c[3])
        : "r"(a[0]), "r"(a[1]), "r"(a[2]), "r"(a[3]), "r"(b[0]), "r"(b[1]));
}

// =====================================================================
// Generic batched GEMM: C[z][M][N] = A[z][M][K] * B[z][N][K]^T
// fp16 in (K-major), fp32 accum via HMMA m16n8k16; C fp32 or fp16.
// Tile 128x128, K-chunk 64 staged in SW128-swizzled smem.
// =====================================================================
__global__ __launch_bounds__(256) void k_gemm(
    const __half* __restrict__ A, const __half* __restrict__ B, void* __restrict__ Cv,
    int K, int ldc, long long sA, long long sB, long long sC, int outHalf)
{
    __shared__ __align__(1024) char smA[16384];
    __shared__ __align__(1024) char smB[16384];
    const uint32_t aA = smem_u32(smA), aB = smem_u32(smB);
    const int tid = threadIdx.x, wid = tid >> 5, lid = tid & 31;
    const int wm = wid & 1, wn = wid >> 1;           // 2 x 4 warp grid
    const int m0 = blockIdx.x << 7, n0 = blockIdx.y << 7, z = blockIdx.z;
    A += (size_t)z * (size_t)sA;
    B += (size_t)z * (size_t)sB;

    float acc[4][4][4];
    #pragma unroll
    for (int i = 0; i < 4; ++i)
    #pragma unroll
    for (int j = 0; j < 4; ++j)
    #pragma unroll
    for (int k = 0; k < 4; ++k) acc[i][j][k] = 0.f;

    // A: row = wm*64 + mt*16 + (lid&15); k-unit(16B) = s*2 + (lid>>4)
    const int arow = wm*64 + (lid & 15);
    const uint32_t ahi = (uint32_t)(lid >> 4) << 4;           // 0 or 16 bytes
    // B: row = wn*32 + (2p + (g>>1))*8 + (lid&7); unit = s*2 + (g&1)
    const int g = lid >> 3;
    const int brow = wn*32 + ((g >> 1) << 3) + (lid & 7);
    const uint32_t bhi = (uint32_t)(g & 1) << 4;

    const int nch = K >> 6, kq = K >> 3;

    for (int c = 0; c < nch; ++c){
        const uint4* a4 = (const uint4*)(A + (size_t)m0 * K) + c * 8;
        const uint4* b4 = (const uint4*)(B + (size_t)n0 * K) + c * 8;
        #pragma unroll
        for (int it = 0; it < 4; ++it){
            int idx = it * 256 + tid;
            int r = idx >> 3, q = idx & 7;
            uint32_t off = (uint32_t)((r << 7) | (q << 4));
            uint32_t sw = off ^ ((off >> 3) & 0x70);
            *(uint4*)(smA + sw) = a4[(size_t)r * kq + q];
            *(uint4*)(smB + sw) = b4[(size_t)r * kq + q];
        }
        __syncthreads();

        #pragma unroll
        for (int s = 0; s < 4; ++s){
            const uint32_t slo = (uint32_t)s << 5;            // s*32 bytes
            uint32_t af[4][4], bf[4][2];
            #pragma unroll
            for (int mt = 0; mt < 4; ++mt){
                int row = arow + mt*16;
                uint32_t base = (uint32_t)(row << 7);
                uint32_t addr = aA + base + ((slo + ahi) ^ (((uint32_t)(row & 7)) << 4));
                ldm_x4(af[mt], addr);
            }
            #pragma unroll
            for (int p = 0; p < 2; ++p){
                int row = brow + p*16;
                uint32_t base = (uint32_t)(row << 7);
                uint32_t addr = aB + base + ((slo + bhi) ^ (((uint32_t)(row & 7)) << 4));
                uint32_t rr[4];
                ldm_x4(rr, addr);
                bf[2*p][0] = rr[0]; bf[2*p][1] = rr[1];
                bf[2*p+1][0] = rr[2]; bf[2*p+1][1] = rr[3];
            }
            #pragma unroll
            for (int mt = 0; mt < 4; ++mt)
            #pragma unroll
            for (int nt = 0; nt < 4; ++nt)
                mma_f16(acc[mt][nt], af[mt], bf[nt]);
        }
        __syncthreads();
    }

    const int rbase = m0 + wm*64 + (lid >> 2);
    const int cbase = n0 + wn*32 + (lid & 3)*2;
    if (!outHalf){
        float* C = (float*)Cv + (size_t)z * sC;
        #pragma unroll
        for (int mt = 0; mt < 4; ++mt)
        #pragma unroll
        for (int nt = 0; nt < 4; ++nt){
            int r0 = rbase + mt*16, cc = cbase + nt*8;
            *(float2*)(C + (size_t)r0 * ldc + cc)       = make_float2(acc[mt][nt][0], acc[mt][nt][1]);
            *(float2*)(C + (size_t)(r0+8) * ldc + cc)   = make_float2(acc[mt][nt][2], acc[mt][nt][3]);
        }
    } else {
        __half* C = (__half*)Cv + (size_t)z * sC;
        #pragma unroll
        for (int mt = 0; mt < 4; ++mt)
        #pragma unroll
        for (int nt = 0; nt < 4; ++nt){
            int r0 = rbase + mt*16, cc = cbase + nt*8;
            *(__half2*)(C + (size_t)r0 * ldc + cc)     = __floats2half2_rn(acc[mt][nt][0], acc[mt][nt][1]);
            *(__half2*)(C + (size_t)(r0+8) * ldc + cc) = __floats2half2_rn(acc[mt][nt][2], acc[mt][nt][3]);
        }
    }
}

// =====================================================================
// Prep / elementwise kernels
// =====================================================================
__global__ void k_prep_xA(const float2* __restrict__ x){
    int idx = blockIdx.x * 256 + threadIdx.x;      // 4096*1024
    int m = idx >> 10, ka = idx & 1023;
    float v = (ka < 512) ? x[(size_t)m*512 + ka].x : x[(size_t)m*512 + ka - 512].y;
    __half h, l; hsplit(v, h, l);
    size_t b = (size_t)m * 2048;
    gAq[b+ka] = h; gAq[b+1024+ka] = l;
}

__global__ void k_prep_qkvB(const float* __restrict__ wq_r, const float* __restrict__ wq_i,
                            const float* __restrict__ wkv_r, const float* __restrict__ wkv_i){
    int idx = blockIdx.x * 256 + threadIdx.x;      // 3072*1024
    int n = idx >> 10, k = idx & 1023;
    int ka = k & 511, isb = k >> 9;
    int im = n >= 1536;
    int c = im ? n - 1536 : n;
    const float* Wr = (c < 512) ? wq_r : wkv_r;
    const float* Wi = (c < 512) ? wq_i : wkv_i;
    int cc = (c < 512) ? c : c - 512;
    int ldw = (c < 512) ? 512 : 1024;
    float wr = Wr[(size_t)ka*ldw + cc], wi = Wi[(size_t)ka*ldw + cc];
    float v = im ? (isb ? wr : wi) : (isb ? -wi : wr);
    __half h = __float2half_rn(v);
    size_t b = (size_t)n * 2048;
    gBq[b+k] = h; gBq[b+1024+k] = h;
}

__global__ void k_prep_rel(const float* __restrict__ rel){
    int idx = blockIdx.x * 256 + threadIdx.x;
    if (idx < 1025*64) gBe[idx] = __float2half_rn(rel[idx]);
}

__global__ __launch_bounds__(256) void k_prep_attn(){
    __shared__ float sVr[64][65], sVi[64][65];
    const int bh = blockIdx.x, n0 = blockIdx.y << 6;
    const int b = bh >> 3, h = bh & 7;
    const int tid = threadIdx.x;
    const int dl = tid & 63;
    #pragma unroll
    for (int p = 0; p < 16; ++p){
        int nl = (p << 2) + (tid >> 6);
        int n = n0 + nl;
        size_t mrow = ((size_t)b*1024 + n) * 3072;
        int hd = h*64 + dl;
        float qr = gCq[mrow + hd],        qi = gCq[mrow + 1536 + hd];
        float kr = gCq[mrow + 512 + hd],  ki = gCq[mrow + 2048 + hd];
        float vr = gCq[mrow + 1024 + hd], vi = gCq[mrow + 2560 + hd];
        __half qh, ql;  hsplit(qr, qh, ql);
        __half ih, il;  hsplit(qi, ih, il);
        size_t ab = ((size_t)bh*1024 + n) * 256;
        gAs[ab+dl] = qh;     gAs[ab+64+dl] = ih;
        gAs[ab+128+dl] = ql; gAs[ab+192+dl] = il;
        __half kh = __float2half_rn(kr);
        __half nh = __float2half_rn(-ki);
        __half kih = __float2half_rn(ki);
        size_t bb = ((size_t)bh*2048 + n) * 256;
        gBs[bb+dl] = kh;      gBs[bb+64+dl] = nh;
        gBs[bb+128+dl] = kh;  gBs[bb+192+dl] = nh;
        size_t b2 = ((size_t)bh*2048 + 1024 + n) * 256;
        gBs[b2+dl] = kih;     gBs[b2+64+dl] = kh;
        gBs[b2+128+dl] = kih; gBs[b2+192+dl] = kh;
        gAe[((size_t)bh*2048 + n)*64 + dl] = __float2half_rn(qr);
        gAe[((size_t)bh*2048 + 1024 + n)*64 + dl] = __float2half_rn(qi);
        sVr[nl][dl] = vr; sVi[nl][dl] = vi;
    }
    __syncthreads();
    #pragma unroll
    for (int p = 0; p < 16; ++p){
        int d = (p << 2) + (tid >> 6);
        int n_ = tid & 63;
        __half h1 = __float2half_rn(sVr[n_][d]);
        __half h2 = __float2half_rn(sVi[n_][d]);
        size_t r1 = ((size_t)bh*128 + d)      * 2048 + n0 + n_;
        size_t r2 = ((size_t)bh*128 + 64 + d) * 2048 + n0 + n_;
        gBpv[r1] = h1; gBpv[r1+1024] = h1;
        gBpv[r2] = h2; gBpv[r2+1024] = h2;
    }
}

__global__ __launch_bounds__(256) void k_softmax(){
    int rowid = blockIdx.x * 8 + (threadIdx.x >> 5);
    int lane = threadIdx.x & 31;
    int bh = rowid >> 10, i = rowid & 1023;
    const __half* S = gS + ((size_t)bh*1024 + i) * 2048;
    const __half* Rr = gR + ((size_t)bh*2048 + i) * 1152;
    const __half* Ri = gR + ((size_t)bh*2048 + 1024 + i) * 1152;
    float mv[32], mx = -1e30f;
    #pragma unroll
    for (int t = 0; t < 32; ++t){
        int j = t*32 + lane;
        int u = i - j; u = u < -512 ? -512 : (u > 512 ? 512 : u); u += 512;
        float sr = __half2float(S[j])        + __half2float(Rr[u]);
        float si = __half2float(S[1024 + j]) + __half2float(Ri[u]);
        float m = 0.125f * sqrtf(sr*sr + si*si);
        mv[t] = m; mx = fmaxf(mx, m);
    }
    #pragma unroll
    for (int o = 16; o > 0; o >>= 1) mx = fmaxf(mx, __shfl_xor_sync(0xffffffffu, mx, o));
    float s = 0.f;
    #pragma unroll
    for (int t = 0; t < 32; ++t){ float e = __expf(mv[t] - mx); mv[t] = e; s += e; }
    #pragma unroll
    for (int o = 16; o > 0; o >>= 1) s += __shfl_xor_sync(0xffffffffu, s, o);
    float inv = 1.f / s;
    size_t pb = ((size_t)bh*1024 + i) * 2048;
    #pragma unroll
    for (int t = 0; t < 32; ++t){
        int j = t*32 + lane;
        __half h, l; hsplit(mv[t] * inv, h, l);
        gP[pb+j] = h; gP[pb+1024+j] = l;
    }
}

__global__ void k_prep_outA(){
    int idx = blockIdx.x * 256 + threadIdx.x;   // 4096*1024
    int m = idx >> 10, e = idx & 1023;
    int b = m >> 10, n = m & 1023;
    int eh = e & 511;
    int h = eh >> 6, d = eh & 63;
    float v = gCpv[(((size_t)(b*8 + h))*1024 + n)*128 + ((e >> 9) ? 64 : 0) + d];
    __half hh, ll; hsplit(v, hh, ll);
    size_t ab = (size_t)m * 2048;
    gAo[ab+e] = hh; gAo[ab+1024+e] = ll;
}

__global__ void k_prep_outB(const float* __restrict__ wo_r, const float* __restrict__ wo_i){
    int idx = blockIdx.x * 256 + threadIdx.x;   // 1024*1024
    int n = idx >> 10, k = idx & 1023;
    int c = n & 511, ka = k & 511;
    float wr = wo_r[(size_t)ka*512 + c], wi = wo_i[(size_t)ka*512 + c];
    float v = (n < 512) ? ((k < 512) ? wr : -wi) : ((k < 512) ? wi : wr);
    __half h = __float2half_rn(v);
    size_t bb = (size_t)n * 2048;
    gBo[bb+k] = h; gBo[bb+1024+k] = h;
}

__global__ void k_final(const float* __restrict__ bo_r, const float* __restrict__ bo_i,
                        float2* __restrict__ out){
    int idx = blockIdx.x * 256 + threadIdx.x;   // 4096*512
    int m = idx >> 9, c = idx & 511;
    out[(size_t)m*512 + c] = make_float2(gCo[(size_t)m*1024 + c]       + bo_r[c],
                                         gCo[(size_t)m*1024 + 512 + c] + bo_i[c]);
}

// =====================================================================
extern "C" void kernel_launch(void* const* d_in, const int* in_sizes, int n_in,
                              void* d_out, int out_size)
{
    const float2* x    = (const float2*)d_in[0];
    const float* wq_r  = (const float*)d_in[1];
    const float* wq_i  = (const float*)d_in[2];
    const float* wkv_r = (const float*)d_in[3];
    const float* wkv_i = (const float*)d_in[4];
    const float* wo_r  = (const float*)d_in[5];
    const float* wo_i  = (const float*)d_in[6];
    const float* bo_r  = (const float*)d_in[7];
    const float* bo_i  = (const float*)d_in[8];
    const float* rel   = (const float*)d_in[9];

    void *pAq,*pBq,*pCq,*pAs,*pBs,*pS,*pAe,*pBe,*pR,*pP,*pBpv,*pCpv,*pAo,*pBo,*pCo;
    cudaGetSymbolAddress(&pAq, gAq);   cudaGetSymbolAddress(&pBq, gBq);
    cudaGetSymbolAddress(&pCq, gCq);   cudaGetSymbolAddress(&pAs, gAs);
    cudaGetSymbolAddress(&pBs, gBs);   cudaGetSymbolAddress(&pS,  gS);
    cudaGetSymbolAddress(&pAe, gAe);   cudaGetSymbolAddress(&pBe, gBe);
    cudaGetSymbolAddress(&pR,  gR);    cudaGetSymbolAddress(&pP,  gP);
    cudaGetSymbolAddress(&pBpv,gBpv);  cudaGetSymbolAddress(&pCpv,gCpv);
    cudaGetSymbolAddress(&pAo, gAo);   cudaGetSymbolAddress(&pBo, gBo);
    cudaGetSymbolAddress(&pCo, gCo);

    k_prep_xA  <<<16384, 256>>>(x);
    k_prep_qkvB<<<12288, 256>>>(wq_r, wq_i, wkv_r, wkv_i);
    k_prep_rel <<<257, 256>>>(rel);
    k_prep_outB<<<4096, 256>>>(wo_r, wo_i);

    // QKV: C[4096,3072] = A[4096,2048] * B[3072,2048]^T
    k_gemm<<<dim3(32,24,1), 256>>>((__half*)pAq, (__half*)pBq, pCq,
        2048, 3072, 0LL, 0LL, 0LL, 0);
    k_prep_attn<<<dim3(32,16), 256>>>();
    // S: per bh, [1024,2048] = A[1024,256]*B[2048,256]^T, fp16 out
    k_gemm<<<dim3(8,16,32), 256>>>((__half*)pAs, (__half*)pBs, pS,
        256, 2048, 1024LL*256, 2048LL*256, 1024LL*2048, 1);
    // REL: per bh, [2048,1152] = A[2048,64]*B[1152,64]^T (B broadcast), fp16 out
    k_gemm<<<dim3(16,9,32), 256>>>((__half*)pAe, (__half*)pBe, pR,
        64, 1152, 2048LL*64, 0LL, 2048LL*1152, 1);
    k_softmax<<<4096, 256>>>();
    // PV: per bh, [1024,128] = P[1024,2048]*V[128,2048]^T
    k_gemm<<<dim3(8,1,32), 256>>>((__half*)pP, (__half*)pBpv, pCpv,
        2048, 128, 1024LL*2048, 128LL*2048, 1024LL*128, 0);
    k_prep_outA<<<16384, 256>>>();
    // OUT: [4096,1024] = A[4096,2048]*B[1024,2048]^T
    k_gemm<<<dim3(32,8,1), 256>>>((__half*)pAo, (__half*)pBo, pCo,
        2048, 1024, 0LL, 0LL, 0LL, 0);
    k_final<<<8192, 256>>>(bo_r, bo_i, (float2*)d_out);
}

// round 9
// speedup vs baseline: 4.1452x; 1.1178x over previous
#include <cuda_runtime.h>
#include <cuda_bf16.h>
#include <cuda_fp16.h>
#include <stdint.h>
#include <math.h>

// ---------------- scratch (__device__ globals; allocation-free) ----------------
__device__ __half gAq[(size_t)4096*2048];
__device__ __half gBq[(size_t)3072*2048];
__device__ float  gCq[(size_t)4096*3072];
__device__ __half gAs[(size_t)32*1024*256];
__device__ __half gBs[(size_t)32*2048*256];
__device__ __half gS [(size_t)32*1024*2048];
__device__ __half gAe[(size_t)32*2048*64];
__device__ __half gBe[(size_t)1152*64];        // rows >=1025 stay zero
__device__ __half gR [(size_t)32*2048*1152];
__device__ __half gP [(size_t)32*1024*2048];
__device__ __half gBpv[(size_t)32*128*2048];
__device__ float  gCpv[(size_t)32*1024*128];
__device__ __half gAo[(size_t)4096*2048];
__device__ __half gBo[(size_t)1024*2048];
__device__ float  gCo[(size_t)4096*1024];

// ---------------- helpers ----------------
__device__ __forceinline__ uint32_t smem_u32(const void* p){
    uint32_t a;
    asm("{ .reg .u64 t; cvta.to.shared.u64 t, %1; cvt.u32.u64 %0, t; }" : "=r"(a) : "l"(p));
    return a;
}
__device__ __forceinline__ void hsplit(float v, __half& h, __half& l){
    h = __float2half_rn(v);
    l = __float2half_rn(v - __half2float(h));
}
__device__ __forceinline__ void ldm_x4(uint32_t* r, uint32_t addr){
    asm volatile("ldmatrix.sync.aligned.m8n8.x4.shared.b16 {%0,%1,%2,%3}, [%4];"
                 : "=r"(r[0]), "=r"(r[1]), "=r"(r[2]), "=r"(r[3]) : "r"(addr));
}
__device__ __forceinline__ void mma_f16(float* c, const uint32_t* a, const uint32_t* b){
    asm volatile(
        "mma.sync.aligned.m16n8k16.row.col.f32.f16.f16.f32 "
        "{%0,%1,%2,%3}, {%4,%5,%6,%7}, {%8,%9}, {%0,%1,%2,%3};"
        : "+f"(c[0]), "+f"(c[1]), "+f"(c[2]), "+f"(c[3])
        : "r"(a[0]), "r"(a[1]), "r"(a[2]), "r"(a[3]), "r"(b[0]), "r"(b[1]));
}
__device__ __forceinline__ void cp16(uint32_t saddr, const void* gptr){
    asm volatile("cp.async.cg.shared.global [%0], [%1], 16;"
                 :: "r"(saddr), "l"(gptr) : "memory");
}

// =====================================================================
// Generic batched GEMM: C[z][M][N] = A[z][M][K] * B[z][N][K]^T
// fp16 in (K-major), fp32 accum via HMMA m16n8k16; C fp32 or fp16.
// Tile 128x128, K-chunk 64, 3-stage cp.async pipeline, SW128 smem.
// =====================================================================
#define GSMEM (3*32768 + 1024)
__global__ __launch_bounds__(256, 2) void k_gemm(
    const __half* __restrict__ A, const __half* __restrict__ B, void* __restrict__ Cv,
    int K, int ldc, long long sA, long long sB, long long sC, int outHalf)
{
    extern __shared__ char smraw[];
    const uint32_t aBase = (smem_u32(smraw) + 1023u) & ~1023u;
    const int tid = threadIdx.x, wid = tid >> 5, lid = tid & 31;
    const int wm = wid & 1, wn = wid >> 1;           // 2 x 4 warp grid
    const int m0 = blockIdx.x << 7, n0 = blockIdx.y << 7, z = blockIdx.z;
    A += (size_t)z * (size_t)sA;
    B += (size_t)z * (size_t)sB;

    float acc[4][4][4];
    #pragma unroll
    for (int i = 0; i < 4; ++i)
    #pragma unroll
    for (int j = 0; j < 4; ++j)
    #pragma unroll
    for (int k = 0; k < 4; ++k) acc[i][j][k] = 0.f;

    // A: row = wm*64 + mt*16 + (lid&15); k-unit(16B) = s*2 + (lid>>4)
    const int arow = wm*64 + (lid & 15);
    const uint32_t ahi = (uint32_t)(lid >> 4) << 4;           // 0 or 16 bytes
    // B: row = wn*32 + (2p + (g>>1))*8 + (lid&7); unit = s*2 + (g&1)
    const int g = lid >> 3;
    const int brow = wn*32 + ((g >> 1) << 3) + (lid & 7);
    const uint32_t bhi = (uint32_t)(g & 1) << 4;

    const int nch = K >> 6, kq = K >> 3;
    // per-thread load coordinates (4 vectors for A, 4 for B per stage)
    const int lr = tid >> 3, lq = tid & 7;                    // covers rows tid>>3 + 32*it

    // issue stage cidx into buffer cidx%3
    auto issue = [&](int cidx){
        const int st = cidx - (cidx/3)*3;
        const uint32_t dA = aBase + (uint32_t)st * 32768u;
        const uint32_t dB = dA + 16384u;
        const uint4* a4 = (const uint4*)(A + (size_t)m0 * K) + cidx * 8;
        const uint4* b4 = (const uint4*)(B + (size_t)n0 * K) + cidx * 8;
        #pragma unroll
        for (int it = 0; it < 4; ++it){
            int r = lr + it*32;
            uint32_t off = (uint32_t)((r << 7) | (lq << 4));
            uint32_t sw = off ^ ((off >> 3) & 0x70);
            cp16(dA + sw, a4 + (size_t)r * kq + lq);
            cp16(dB + sw, b4 + (size_t)r * kq + lq);
        }
    };

    if (0 < nch) issue(0);
    asm volatile("cp.async.commit_group;" ::: "memory");
    if (1 < nch) issue(1);
    asm volatile("cp.async.commit_group;" ::: "memory");

    for (int c = 0; c < nch; ++c){
        if (c + 2 < nch) issue(c + 2);
        asm volatile("cp.async.commit_group;" ::: "memory");
        asm volatile("cp.async.wait_group %0;" :: "n"(2));
        __syncthreads();

        const int st = c - (c/3)*3;
        const uint32_t aA = aBase + (uint32_t)st * 32768u;
        const uint32_t aB = aA + 16384u;
        #pragma unroll
        for (int s = 0; s < 4; ++s){
            const uint32_t slo = (uint32_t)s << 5;            // s*32 bytes
            uint32_t af[4][4], bf[4][2];
            #pragma unroll
            for (int mt = 0; mt < 4; ++mt){
                int row = arow + mt*16;
                uint32_t base = (uint32_t)(row << 7);
                uint32_t addr = aA + base + ((slo + ahi) ^ (((uint32_t)(row & 7)) << 4));
                ldm_x4(af[mt], addr);
            }
            #pragma unroll
            for (int p = 0; p < 2; ++p){
                int row = brow + p*16;
                uint32_t base = (uint32_t)(row << 7);
                uint32_t addr = aB + base + ((slo + bhi) ^ (((uint32_t)(row & 7)) << 4));
                uint32_t rr[4];
                ldm_x4(rr, addr);
                bf[2*p][0] = rr[0]; bf[2*p][1] = rr[1];
                bf[2*p+1][0] = rr[2]; bf[2*p+1][1] = rr[3];
            }
            #pragma unroll
            for (int mt = 0; mt < 4; ++mt)
            #pragma unroll
            for (int nt = 0; nt < 4; ++nt)
                mma_f16(acc[mt][nt], af[mt], bf[nt]);
        }
        __syncthreads();
    }

    const int rbase = m0 + wm*64 + (lid >> 2);
    const int cbase = n0 + wn*32 + (lid & 3)*2;
    if (!outHalf){
        float* C = (float*)Cv + (size_t)z * sC;
        #pragma unroll
        for (int mt = 0; mt < 4; ++mt)
        #pragma unroll
        for (int nt = 0; nt < 4; ++nt){
            int r0 = rbase + mt*16, cc = cbase + nt*8;
            *(float2*)(C + (size_t)r0 * ldc + cc)       = make_float2(acc[mt][nt][0], acc[mt][nt][1]);
            *(float2*)(C + (size_t)(r0+8) * ldc + cc)   = make_float2(acc[mt][nt][2], acc[mt][nt][3]);
        }
    } else {
        __half* C = (__half*)Cv + (size_t)z * sC;
        #pragma unroll
        for (int mt = 0; mt < 4; ++mt)
        #pragma unroll
        for (int nt = 0; nt < 4; ++nt){
            int r0 = rbase + mt*16, cc = cbase + nt*8;
            *(__half2*)(C + (size_t)r0 * ldc + cc)     = __floats2half2_rn(acc[mt][nt][0], acc[mt][nt][1]);
            *(__half2*)(C + (size_t)(r0+8) * ldc + cc) = __floats2half2_rn(acc[mt][nt][2], acc[mt][nt][3]);
        }
    }
}

// =====================================================================
// Prep / elementwise kernels
// =====================================================================
__global__ void k_prep_xA(const float2* __restrict__ x){
    int idx = blockIdx.x * 256 + threadIdx.x;      // 4096*1024
    int m = idx >> 10, ka = idx & 1023;
    float v = (ka < 512) ? x[(size_t)m*512 + ka].x : x[(size_t)m*512 + ka - 512].y;
    __half h, l; hsplit(v, h, l);
    size_t b = (size_t)m * 2048;
    gAq[b+ka] = h; gAq[b+1024+ka] = l;
}

__global__ void k_prep_qkvB(const float* __restrict__ wq_r, const float* __restrict__ wq_i,
                            const float* __restrict__ wkv_r, const float* __restrict__ wkv_i){
    int idx = blockIdx.x * 256 + threadIdx.x;      // 3072*1024
    int n = idx >> 10, k = idx & 1023;
    int ka = k & 511, isb = k >> 9;
    int im = n >= 1536;
    int c = im ? n - 1536 : n;
    const float* Wr = (c < 512) ? wq_r : wkv_r;
    const float* Wi = (c < 512) ? wq_i : wkv_i;
    int cc = (c < 512) ? c : c - 512;
    int ldw = (c < 512) ? 512 : 1024;
    float wr = Wr[(size_t)ka*ldw + cc], wi = Wi[(size_t)ka*ldw + cc];
    float v = im ? (isb ? wr : wi) : (isb ? -wi : wr);
    __half h = __float2half_rn(v);
    size_t b = (size_t)n * 2048;
    gBq[b+k] = h; gBq[b+1024+k] = h;
}

__global__ void k_prep_rel(const float* __restrict__ rel){
    int idx = blockIdx.x * 256 + threadIdx.x;
    if (idx < 1025*64) gBe[idx] = __float2half_rn(rel[idx]);
}

__global__ __launch_bounds__(256) void k_prep_attn(){
    __shared__ float sVr[64][65], sVi[64][65];
    const int bh = blockIdx.x, n0 = blockIdx.y << 6;
    const int b = bh >> 3, h = bh & 7;
    const int tid = threadIdx.x;
    const int dl = tid & 63;
    #pragma unroll
    for (int p = 0; p < 16; ++p){
        int nl = (p << 2) + (tid >> 6);
        int n = n0 + nl;
        size_t mrow = ((size_t)b*1024 + n) * 3072;
        int hd = h*64 + dl;
        float qr = gCq[mrow + hd],        qi = gCq[mrow + 1536 + hd];
        float kr = gCq[mrow + 512 + hd],  ki = gCq[mrow + 2048 + hd];
        float vr = gCq[mrow + 1024 + hd], vi = gCq[mrow + 2560 + hd];
        __half qh, ql;  hsplit(qr, qh, ql);
        __half ih, il;  hsplit(qi, ih, il);
        size_t ab = ((size_t)bh*1024 + n) * 256;
        gAs[ab+dl] = qh;     gAs[ab+64+dl] = ih;
        gAs[ab+128+dl] = ql; gAs[ab+192+dl] = il;
        __half kh = __float2half_rn(kr);
        __half nh = __float2half_rn(-ki);
        __half kih = __float2half_rn(ki);
        size_t bb = ((size_t)bh*2048 + n) * 256;
        gBs[bb+dl] = kh;      gBs[bb+64+dl] = nh;
        gBs[bb+128+dl] = kh;  gBs[bb+192+dl] = nh;
        size_t b2 = ((size_t)bh*2048 + 1024 + n) * 256;
        gBs[b2+dl] = kih;     gBs[b2+64+dl] = kh;
        gBs[b2+128+dl] = kih; gBs[b2+192+dl] = kh;
        gAe[((size_t)bh*2048 + n)*64 + dl] = __float2half_rn(qr);
        gAe[((size_t)bh*2048 + 1024 + n)*64 + dl] = __float2half_rn(qi);
        sVr[nl][dl] = vr; sVi[nl][dl] = vi;
    }
    __syncthreads();
    #pragma unroll
    for (int p = 0; p < 16; ++p){
        int d = (p << 2) + (tid >> 6);
        int n_ = tid & 63;
        __half h1 = __float2half_rn(sVr[n_][d]);
        __half h2 = __float2half_rn(sVi[n_][d]);
        size_t r1 = ((size_t)bh*128 + d)      * 2048 + n0 + n_;
        size_t r2 = ((size_t)bh*128 + 64 + d) * 2048 + n0 + n_;
        gBpv[r1] = h1; gBpv[r1+1024] = h1;
        gBpv[r2] = h2; gBpv[r2+1024] = h2;
    }
}

__global__ __launch_bounds__(256) void k_softmax(){
    int rowid = blockIdx.x * 8 + (threadIdx.x >> 5);
    int lane = threadIdx.x & 31;
    int bh = rowid >> 10, i = rowid & 1023;
    const __half* S = gS + ((size_t)bh*1024 + i) * 2048;
    const __half* Rr = gR + ((size_t)bh*2048 + i) * 1152;
    const __half* Ri = gR + ((size_t)bh*2048 + 1024 + i) * 1152;
    float mv[32], mx = -1e30f;
    #pragma unroll
    for (int t = 0; t < 32; ++t){
        int j = t*32 + lane;
        int u = i - j; u = u < -512 ? -512 : (u > 512 ? 512 : u); u += 512;
        float sr = __half2float(S[j])        + __half2float(Rr[u]);
        float si = __half2float(S[1024 + j]) + __half2float(Ri[u]);
        float m = 0.125f * sqrtf(sr*sr + si*si);
        mv[t] = m; mx = fmaxf(mx, m);
    }
    #pragma unroll
    for (int o = 16; o > 0; o >>= 1) mx = fmaxf(mx, __shfl_xor_sync(0xffffffffu, mx, o));
    float s = 0.f;
    #pragma unroll
    for (int t = 0; t < 32; ++t){ float e = __expf(mv[t] - mx); mv[t] = e; s += e; }
    #pragma unroll
    for (int o = 16; o > 0; o >>= 1) s += __shfl_xor_sync(0xffffffffu, s, o);
    float inv = 1.f / s;
    size_t pb = ((size_t)bh*1024 + i) * 2048;
    #pragma unroll
    for (int t = 0; t < 32; ++t){
        int j = t*32 + lane;
        __half h, l; hsplit(mv[t] * inv, h, l);
        gP[pb+j] = h; gP[pb+1024+j] = l;
    }
}

__global__ void k_prep_outA(){
    int idx = blockIdx.x * 256 + threadIdx.x;   // 4096*1024
    int m = idx >> 10, e = idx & 1023;
    int b = m >> 10, n = m & 1023;
    int eh = e & 511;
    int h = eh >> 6, d = eh & 63;
    float v = gCpv[(((size_t)(b*8 + h))*1024 + n)*128 + ((e >> 9) ? 64 : 0) + d];
    __half hh, ll; hsplit(v, hh, ll);
    size_t ab = (size_t)m * 2048;
    gAo[ab+e] = hh; gAo[ab+1024+e] = ll;
}

__global__ void k_prep_outB(const float* __restrict__ wo_r, const float* __restrict__ wo_i){
    int idx = blockIdx.x * 256 + threadIdx.x;   // 1024*1024
    int n = idx >> 10, k = idx & 1023;
    int c = n & 511, ka = k & 511;
    float wr = wo_r[(size_t)ka*512 + c], wi = wo_i[(size_t)ka*512 + c];
    float v = (n < 512) ? ((k < 512) ? wr : -wi) : ((k < 512) ? wi : wr);
    __half h = __float2half_rn(v);
    size_t bb = (size_t)n * 2048;
    gBo[bb+k] = h; gBo[bb+1024+k] = h;
}

__global__ void k_final(const float* __restrict__ bo_r, const float* __restrict__ bo_i,
                        float2* __restrict__ out){
    int idx = blockIdx.x * 256 + threadIdx.x;   // 4096*512
    int m = idx >> 9, c = idx & 511;
    out[(size_t)m*512 + c] = make_float2(gCo[(size_t)m*1024 + c]       + bo_r[c],
                                         gCo[(size_t)m*1024 + 512 + c] + bo_i[c]);
}

// =====================================================================
extern "C" void kernel_launch(void* const* d_in, const int* in_sizes, int n_in,
                              void* d_out, int out_size)
{
    const float2* x    = (const float2*)d_in[0];
    const float* wq_r  = (const float*)d_in[1];
    const float* wq_i  = (const float*)d_in[2];
    const float* wkv_r = (const float*)d_in[3];
    const float* wkv_i = (const float*)d_in[4];
    const float* wo_r  = (const float*)d_in[5];
    const float* wo_i  = (const float*)d_in[6];
    const float* bo_r  = (const float*)d_in[7];
    const float* bo_i  = (const float*)d_in[8];
    const float* rel   = (const float*)d_in[9];

    cudaFuncSetAttribute(k_gemm, cudaFuncAttributeMaxDynamicSharedMemorySize, GSMEM);

    void *pAq,*pBq,*pCq,*pAs,*pBs,*pS,*pAe,*pBe,*pR,*pP,*pBpv,*pCpv,*pAo,*pBo,*pCo;
    cudaGetSymbolAddress(&pAq, gAq);   cudaGetSymbolAddress(&pBq, gBq);
    cudaGetSymbolAddress(&pCq, gCq);   cudaGetSymbolAddress(&pAs, gAs);
    cudaGetSymbolAddress(&pBs, gBs);   cudaGetSymbolAddress(&pS,  gS);
    cudaGetSymbolAddress(&pAe, gAe);   cudaGetSymbolAddress(&pBe, gBe);
    cudaGetSymbolAddress(&pR,  gR);    cudaGetSymbolAddress(&pP,  gP);
    cudaGetSymbolAddress(&pBpv,gBpv);  cudaGetSymbolAddress(&pCpv,gCpv);
    cudaGetSymbolAddress(&pAo, gAo);   cudaGetSymbolAddress(&pBo, gBo);
    cudaGetSymbolAddress(&pCo, gCo);

    k_prep_xA  <<<16384, 256>>>(x);
    k_prep_qkvB<<<12288, 256>>>(wq_r, wq_i, wkv_r, wkv_i);
    k_prep_rel <<<257, 256>>>(rel);
    k_prep_outB<<<4096, 256>>>(wo_r, wo_i);

    // QKV: C[4096,3072] = A[4096,2048] * B[3072,2048]^T
    k_gemm<<<dim3(32,24,1), 256, GSMEM>>>((__half*)pAq, (__half*)pBq, pCq,
        2048, 3072, 0LL, 0LL, 0LL, 0);
    k_prep_attn<<<dim3(32,16), 256>>>();
    // S: per bh, [1024,2048] = A[1024,256]*B[2048,256]^T, fp16 out
    k_gemm<<<dim3(8,16,32), 256, GSMEM>>>((__half*)pAs, (__half*)pBs, pS,
        256, 2048, 1024LL*256, 2048LL*256, 1024LL*2048, 1);
    // REL: per bh, [2048,1152] = A[2048,64]*B[1152,64]^T (B broadcast), fp16 out
    k_gemm<<<dim3(16,9,32), 256, GSMEM>>>((__half*)pAe, (__half*)pBe, pR,
        64, 1152, 2048LL*64, 0LL, 2048LL*1152, 1);
    k_softmax<<<4096, 256>>>();
    // PV: per bh, [1024,128] = P[1024,2048]*V[128,2048]^T
    k_gemm<<<dim3(8,1,32), 256, GSMEM>>>((__half*)pP, (__half*)pBpv, pCpv,
        2048, 128, 1024LL*2048, 128LL*2048, 1024LL*128, 0);
    k_prep_outA<<<16384, 256>>>();
    // OUT: [4096,1024] = A[4096,2048]*B[1024,2048]^T
    k_gemm<<<dim3(32,8,1), 256, GSMEM>>>((__half*)pAo, (__half*)pBo, pCo,
        2048, 1024, 0LL, 0LL, 0LL, 0);
    k_final<<<8192, 256>>>(bo_r, bo_i, (float2*)d_out);
}